// round 10
// baseline (speedup 1.0000x reference)
#include <cuda_runtime.h>
#include <math.h>

#define NT 4096
#define NA 4096
#define NS 1024
#define NALL 9216
#define FEAT 128
#define COM 64
#define MPD 64
#define MAXN 192
#define FGH_TH 0.1f
#define FGP_TH 0.2f
#define SEM_TH 0.1f

// ---------------- scratch (device globals; no allocations allowed) ----------------
__device__ float g_Yt  [NT * 256];
__device__ float g_Ya  [NA * 256];
__device__ float g_Ys  [NS * 256];
__device__ float g_Ypap[NT * 128];
__device__ float g_Ypsp[NT * 128];
__device__ float g_Yfpa[NT * 256];
__device__ float g_Yfps[NT * 256];
__device__ float g_Ytha[NT * 128];
__device__ float g_Yths[NT * 128];

__device__ float g_Mg  [16777216];
__device__ float g_Mpap[16777216];
__device__ float g_Mpsp[16777216];
__device__ float g_Mfa [16777216];
__device__ float g_Mfs [16777216];
__device__ float g_Msa [16777216];
__device__ float g_Mss [16777216];
__device__ float g_simA[16777216];   // reused later as 'pre' (dead after HA GEMM)
__device__ float g_simS[NS * NS];

__device__ float g_fpA[NT * FEAT];
__device__ float g_fpS[NT * FEAT];
__device__ float g_HA [NA * COM];
__device__ float g_HS [NS * COM];
__device__ float g_thA[NT * COM];
__device__ float g_thS[NT * COM];

__device__ int   g_idxA[NT * MAXN];
__device__ int   g_idxS[NT * MAXN];
__device__ float g_valA[NT * MAXN];
__device__ float g_valS[NT * MAXN];
__device__ int   g_cntA[NT];
__device__ int   g_cntS[NT];

__device__ float g_cs   [7 * NT];
__device__ float g_alpha[7 * NT];
__device__ float g_cspre[NT];
__device__ float g_rspre[NT];

__device__ float g_XW1[NT * 64];
__device__ float g_X1 [NT * 64];
__device__ float g_Z2 [NT * 3];

// ---------------- kernels ----------------

// Per-head weighted row-L2-normalize + pack: Y[row, h*D + d] = x_d*w_hd / max(||x∘w_h||,1e-12)
__global__ void build_y_kernel(const float* __restrict__ X, const float* __restrict__ W,
                               int D, float* __restrict__ Y) {
    int row = blockIdx.x;
    int t = threadIdx.x;             // 128 threads
    __shared__ float red[128];
    for (int h = 0; h < 2; h++) {
        float v = 0.0f;
        if (t < D) v = X[(size_t)row * D + t] * W[h * D + t];
        red[t] = v * v;
        __syncthreads();
        for (int s = 64; s > 0; s >>= 1) {
            if (t < s) red[t] += red[t + s];
            __syncthreads();
        }
        float nrm = fmaxf(sqrtf(red[0]), 1e-12f);
        __syncthreads();
        if (t < D) Y[(size_t)row * (2 * D) + h * D + t] = v / nrm;
    }
}

// Deterministic nonzero compaction (warp-per-row, ballot prefix -> ascending order).
__global__ void compact_adj_kernel(const float* __restrict__ adj, int lda, int col0, int ncols,
                                   int* __restrict__ idx, float* __restrict__ val,
                                   int* __restrict__ cnt) {
    int row = blockIdx.x * (blockDim.x / 32) + (threadIdx.x >> 5);
    int lane = threadIdx.x & 31;
    if (row >= NT) return;
    const float* base = adj + (size_t)row * lda + col0;
    int c = 0;
    for (int b = 0; b < ncols; b += 32) {
        int j = b + lane;
        float a = base[j];                   // ncols is a multiple of 32
        unsigned m = __ballot_sync(0xffffffffu, a != 0.0f);
        if (a != 0.0f) {
            int p = c + __popc(m & ((1u << lane) - 1u));
            if (p < MAXN) {
                idx[(size_t)row * MAXN + p] = j;
                val[(size_t)row * MAXN + p] = a;
            }
        }
        c += __popc(m);
    }
    if (lane == 0) cnt[row] = (c < MAXN) ? c : MAXN;
}

// dst[row,:] = sum_nbr val * src[nbr,:] (+ bias). blockDim.x == W.
__global__ void sp_gather_kernel(const int* __restrict__ idx, const float* __restrict__ val,
                                 const int* __restrict__ cnt, const float* __restrict__ src,
                                 int W, const float* __restrict__ bias, float* __restrict__ dst) {
    int row = blockIdx.x;
    int t = threadIdx.x;
    float acc = bias ? bias[t] : 0.0f;
    int n = cnt[row];
    const int* ip = idx + (size_t)row * MAXN;
    const float* vp = val + (size_t)row * MAXN;
    for (int p = 0; p < n; p++) {
        acc += vp[p] * src[(size_t)ip[p] * W + t];
    }
    dst[(size_t)row * W + t] = acc;
}

// Triangular SYRK: C = thresh(scale * Y Y^T, th), exact-symmetric mirror of
// off-diagonal tiles, fused full-matrix row sums (== col sums) into colsum.
// 128x128 tile, BK=16, 256 threads, 8x8 per thread (split-64 conflict-free mapping).
__global__ __launch_bounds__(256) void syrk_thresh_kernel(
    const float* __restrict__ Y, int N, int K, float scale, float th,
    float* __restrict__ C, float* __restrict__ colsum) {
    int bi = blockIdx.y, bj = blockIdx.x;
    if (bj < bi) return;
    __shared__ float As[16][128];
    __shared__ float Bs[16][128];
    __shared__ float s_col[128];
    int tid = threadIdx.x;
    int tx = tid & 15, ty = tid >> 4;
    const float* Arow = Y + (size_t)bi * 128 * K;
    const float* Brow = Y + (size_t)bj * 128 * K;
    float acc[8][8];
#pragma unroll
    for (int i = 0; i < 8; i++)
#pragma unroll
        for (int j = 0; j < 8; j++) acc[i][j] = 0.0f;

    for (int k0 = 0; k0 < K; k0 += 16) {
#pragma unroll
        for (int l = 0; l < 2; l++) {
            int f = tid * 2 + l;     // 0..511
            int r = f >> 2;
            int q = f & 3;
            float4 a = *(const float4*)(Arow + (size_t)r * K + k0 + q * 4);
            As[q * 4 + 0][r] = a.x; As[q * 4 + 1][r] = a.y;
            As[q * 4 + 2][r] = a.z; As[q * 4 + 3][r] = a.w;
            float4 b = *(const float4*)(Brow + (size_t)r * K + k0 + q * 4);
            Bs[q * 4 + 0][r] = b.x; Bs[q * 4 + 1][r] = b.y;
            Bs[q * 4 + 2][r] = b.z; Bs[q * 4 + 3][r] = b.w;
        }
        __syncthreads();
#pragma unroll
        for (int k = 0; k < 16; k++) {
            float4 a0 = *(const float4*)&As[k][ty * 4];
            float4 a1 = *(const float4*)&As[k][64 + ty * 4];
            float4 b0 = *(const float4*)&Bs[k][tx * 4];
            float4 b1 = *(const float4*)&Bs[k][64 + tx * 4];
            float av[8] = {a0.x, a0.y, a0.z, a0.w, a1.x, a1.y, a1.z, a1.w};
            float bv[8] = {b0.x, b0.y, b0.z, b0.w, b1.x, b1.y, b1.z, b1.w};
#pragma unroll
            for (int i = 0; i < 8; i++)
#pragma unroll
                for (int j = 0; j < 8; j++) acc[i][j] += av[i] * bv[j];
        }
        __syncthreads();
    }

    // threshold in place
#pragma unroll
    for (int i = 0; i < 8; i++)
#pragma unroll
        for (int j = 0; j < 8; j++) {
            float c = acc[i][j] * scale;
            acc[i][j] = (c < th) ? 0.0f : c;
        }

    // direct tile store (rows bi-block, cols bj-block) + row sums
#pragma unroll
    for (int ri = 0; ri < 2; ri++) {
#pragma unroll
        for (int ii = 0; ii < 4; ii++) {
            int i = ri * 4 + ii;
            int row = bi * 128 + ri * 64 + ty * 4 + ii;
            float4 w0 = make_float4(acc[i][0], acc[i][1], acc[i][2], acc[i][3]);
            float4 w1 = make_float4(acc[i][4], acc[i][5], acc[i][6], acc[i][7]);
            *(float4*)(C + (size_t)row * N + bj * 128 + tx * 4) = w0;
            *(float4*)(C + (size_t)row * N + bj * 128 + 64 + tx * 4) = w1;
            if (colsum) {
                float rs = w0.x + w0.y + w0.z + w0.w + w1.x + w1.y + w1.z + w1.w;
#pragma unroll
                for (int off = 8; off >= 1; off >>= 1)
                    rs += __shfl_down_sync(0xffffffffu, rs, off, 16);
                if (tx == 0) atomicAdd(&colsum[row], rs);
            }
        }
    }

    if (bi != bj) {
        // mirror store: transposed tile to (bj-block rows, bi-block cols).
        // float4 over the ii dimension (consecutive columns of the mirror row).
#pragma unroll
        for (int ci = 0; ci < 2; ci++) {
#pragma unroll
            for (int jj = 0; jj < 4; jj++) {
                int j = ci * 4 + jj;
                int r2 = bj * 128 + ci * 64 + tx * 4 + jj;
                float4 w0 = make_float4(acc[0][j], acc[1][j], acc[2][j], acc[3][j]);
                float4 w1 = make_float4(acc[4][j], acc[5][j], acc[6][j], acc[7][j]);
                *(float4*)(C + (size_t)r2 * N + bi * 128 + ty * 4) = w0;
                *(float4*)(C + (size_t)r2 * N + bi * 128 + 64 + ty * 4) = w1;
            }
        }
        if (colsum) {
            // mirror rows' sums == direct tile column sums
            if (tid < 128) s_col[tid] = 0.0f;
            __syncthreads();
#pragma unroll
            for (int ci = 0; ci < 2; ci++)
#pragma unroll
                for (int jj = 0; jj < 4; jj++) {
                    int j = ci * 4 + jj;
                    float cp = 0.0f;
#pragma unroll
                    for (int i = 0; i < 8; i++) cp += acc[i][j];
                    atomicAdd(&s_col[ci * 64 + tx * 4 + jj], cp);
                }
            __syncthreads();
            if (tid < 128) atomicAdd(&colsum[bj * 128 + tid], s_col[tid]);
        }
    }
}

// C[M,64] = A[M,K] @ B[K,64] (+bias, optional relu). 64x64 tile, BK=32.
__global__ __launch_bounds__(256) void gemm_n64_kernel(
    const float* __restrict__ A, const float* __restrict__ B,
    const float* __restrict__ bias, float* __restrict__ C,
    int M, int K, int relu) {
    __shared__ float As[32][65];
    __shared__ float Bs[32][64];
    int bm = blockIdx.x;
    int tid = threadIdx.x;
    int tx = tid & 15, ty = tid >> 4;
    float acc[4][4];
#pragma unroll
    for (int i = 0; i < 4; i++)
#pragma unroll
        for (int j = 0; j < 4; j++) acc[i][j] = 0.0f;

    for (int k0 = 0; k0 < K; k0 += 32) {
#pragma unroll
        for (int l = 0; l < 2; l++) {
            int f = tid * 2 + l;    // 0..511
            int r = f >> 3;
            int q = f & 7;
            float4 a = *(const float4*)(A + (size_t)(bm * 64 + r) * K + k0 + q * 4);
            As[q * 4 + 0][r] = a.x; As[q * 4 + 1][r] = a.y;
            As[q * 4 + 2][r] = a.z; As[q * 4 + 3][r] = a.w;
            int kr = f >> 4;
            int nq = f & 15;
            float4 b = *(const float4*)(B + (size_t)(k0 + kr) * 64 + nq * 4);
            *(float4*)&Bs[kr][nq * 4] = b;
        }
        __syncthreads();
#pragma unroll
        for (int k = 0; k < 32; k++) {
            float a[4], b[4];
#pragma unroll
            for (int i = 0; i < 4; i++) a[i] = As[k][ty * 4 + i];
#pragma unroll
            for (int j = 0; j < 4; j++) b[j] = Bs[k][tx * 4 + j];
#pragma unroll
            for (int i = 0; i < 4; i++)
#pragma unroll
                for (int j = 0; j < 4; j++) acc[i][j] += a[i] * b[j];
        }
        __syncthreads();
    }
#pragma unroll
    for (int i = 0; i < 4; i++) {
        int row = bm * 64 + ty * 4 + i;
        float v[4];
#pragma unroll
        for (int j = 0; j < 4; j++) {
            float c = acc[i][j];
            if (bias) c += bias[tx * 4 + j];
            if (relu) c = fmaxf(c, 0.0f);
            v[j] = c;
        }
        *(float4*)(C + (size_t)row * 64 + tx * 4) = make_float4(v[0], v[1], v[2], v[3]);
    }
}

// Per-column channel-attention coefficients from the 7 colsums + softmaxed weights.
__global__ void alpha_kernel(const float* __restrict__ cs,
                             const float* __restrict__ sg_w, const float* __restrict__ ff_w,
                             const float* __restrict__ f_w,
                             float* __restrict__ alpha, float* __restrict__ cspre) {
    int j = blockIdx.x * blockDim.x + threadIdx.x;
    if (j >= NT) return;
    const float eps = 1e-12f;
    // softmax(sg_agg_w)
    float m1 = fmaxf(sg_w[0], sg_w[1]);
    float e0 = expf(sg_w[0] - m1), e1 = expf(sg_w[1] - m1);
    float wi0 = e0 / (e0 + e1), wi1 = e1 / (e0 + e1);
    // softmax(f_agg_f_w)
    float m2 = fmaxf(ff_w[0], ff_w[1]);
    float f0 = expf(ff_w[0] - m2), f1 = expf(ff_w[1] - m2);
    float wf0 = f0 / (f0 + f1), wf1 = f1 / (f0 + f1);
    // softmax(f_agg_w)
    float m3 = fmaxf(fmaxf(f_w[0], f_w[1]), fmaxf(f_w[2], f_w[3]));
    float o0 = expf(f_w[0] - m3), o1 = expf(f_w[1] - m3);
    float o2 = expf(f_w[2] - m3), o3 = expf(f_w[3] - m3);
    float os = o0 + o1 + o2 + o3;
    float wo0 = o0 / os, wo1 = o1 / os, wo2 = o2 / os, wo3 = o3 / os;

    float cg   = cs[0 * NT + j];
    float cpap = cs[1 * NT + j];
    float cpsp = cs[2 * NT + j];
    float cfa  = cs[3 * NT + j];
    float cfs  = cs[4 * NT + j];
    float csa  = cs[5 * NT + j];
    float css  = cs[6 * NT + j];

    float bpap = cpap / fmaxf(cpap, eps);
    float bpsp = cpsp / fmaxf(cpsp, eps);
    float bfa  = cfa  / fmaxf(cfa,  eps);
    float bfs  = cfs  / fmaxf(cfs,  eps);
    float bsa  = csa  / fmaxf(csa,  eps);
    float bss  = css  / fmaxf(css,  eps);

    float csem = wi0 * bpap + wi1 * bpsp;
    float cfp  = wf0 * bfa  + wf1 * bfs;
    float ctt  = wf0 * bsa  + wf1 * bss;

    float ag   = wo0 / fmaxf(cg, eps);
    float apap = wo1 * wi0 / fmaxf(cpap, eps) / fmaxf(csem, eps);
    float apsp = wo1 * wi1 / fmaxf(cpsp, eps) / fmaxf(csem, eps);
    float afa  = wo2 * wf0 / fmaxf(cfa,  eps) / fmaxf(cfp,  eps);
    float afs  = wo2 * wf1 / fmaxf(cfs,  eps) / fmaxf(cfp,  eps);
    float asa  = wo3 * wf0 / fmaxf(csa,  eps) / fmaxf(ctt,  eps);
    float ass  = wo3 * wf1 / fmaxf(css,  eps) / fmaxf(ctt,  eps);

    alpha[0 * NT + j] = ag;
    alpha[1 * NT + j] = apap;
    alpha[2 * NT + j] = apsp;
    alpha[3 * NT + j] = afa;
    alpha[4 * NT + j] = afs;
    alpha[5 * NT + j] = asa;
    alpha[6 * NT + j] = ass;
    cspre[j] = ag * cg + apap * cpap + apsp * cpsp + afa * cfa + afs * cfs
             + asa * csa + ass * css;
}

// pre[i,j] = sum_m alpha_m[j] * M_m[i,j]; accumulate row sums of pre.
// grid (NT/32, NT/128), block (32, 8); each thread handles 16 rows of one column.
__global__ void combine_kernel(const float* __restrict__ M0, const float* __restrict__ M1,
                               const float* __restrict__ M2, const float* __restrict__ M3,
                               const float* __restrict__ M4, const float* __restrict__ M5,
                               const float* __restrict__ M6,
                               const float* __restrict__ alpha,
                               float* __restrict__ pre, float* __restrict__ rowsum) {
    int j = blockIdx.x * 32 + threadIdx.x;
    float a0 = alpha[0 * NT + j];
    float a1 = alpha[1 * NT + j];
    float a2 = alpha[2 * NT + j];
    float a3 = alpha[3 * NT + j];
    float a4 = alpha[4 * NT + j];
    float a5 = alpha[5 * NT + j];
    float a6 = alpha[6 * NT + j];
#pragma unroll
    for (int r = 0; r < 16; r++) {
        int i = blockIdx.y * 128 + threadIdx.y + r * 8;
        size_t off = (size_t)i * NT + j;
        float v = a0 * M0[off] + a1 * M1[off] + a2 * M2[off] + a3 * M3[off]
                + a4 * M4[off] + a5 * M5[off] + a6 * M6[off];
        pre[off] = v;
        float s = v;
#pragma unroll
        for (int o = 16; o >= 1; o >>= 1) s += __shfl_down_sync(0xffffffffu, s, o);
        if (threadIdx.x == 0) atomicAdd(&rowsum[i], s);
    }
}

// out[i,j] = (pre[i,j] + pre[j,i]) / max(cspre[j] + rspre[j], 1e-12)
__global__ void symnorm_kernel(const float* __restrict__ pre, const float* __restrict__ cspre,
                               const float* __restrict__ rspre, float* __restrict__ out) {
    __shared__ float tile[32][33];
    int bi = blockIdx.y, bj = blockIdx.x;
    int x = threadIdx.x, y = threadIdx.y;
#pragma unroll
    for (int r = 0; r < 4; r++) {
        int yy = y + r * 8;
        tile[yy][x] = pre[(size_t)(bj * 32 + yy) * NT + bi * 32 + x];
    }
    __syncthreads();
#pragma unroll
    for (int r = 0; r < 4; r++) {
        int i = bi * 32 + y + r * 8;
        int j = bj * 32 + x;
        float d = fmaxf(cspre[j] + rspre[j], 1e-12f);
        float v = (pre[(size_t)i * NT + j] + tile[x][y + r * 8]) / d;
        out[(size_t)i * NT + j] = v;
    }
}

// Z2 = X1[4096,64] @ W2[64,3]
__global__ void xw2_kernel(const float* __restrict__ X1, const float* __restrict__ W2,
                           float* __restrict__ Z2) {
    int row = blockIdx.x * blockDim.x + threadIdx.x;
    if (row >= NT) return;
    float a0 = 0, a1 = 0, a2 = 0;
    const float* x = X1 + (size_t)row * 64;
#pragma unroll 8
    for (int k = 0; k < 64; k++) {
        float v = x[k];
        a0 += v * W2[k * 3 + 0];
        a1 += v * W2[k * 3 + 1];
        a2 += v * W2[k * 3 + 2];
    }
    Z2[row * 3 + 0] = a0;
    Z2[row * 3 + 1] = a1;
    Z2[row * 3 + 2] = a2;
}

// logits[row,:] = log_softmax(adj[row,:] @ Z2 + b2)
__global__ void final_logits_kernel(const float* __restrict__ adj, const float* __restrict__ Z2,
                                    const float* __restrict__ b2, float* __restrict__ out) {
    int row = blockIdx.x;
    int t = threadIdx.x;   // 128
    float a0 = 0, a1 = 0, a2 = 0;
    const float* ar = adj + (size_t)row * NT;
    for (int k = t; k < NT; k += 128) {
        float w = ar[k];
        a0 += w * Z2[k * 3 + 0];
        a1 += w * Z2[k * 3 + 1];
        a2 += w * Z2[k * 3 + 2];
    }
    __shared__ float s0[128], s1[128], s2[128];
    s0[t] = a0; s1[t] = a1; s2[t] = a2;
    __syncthreads();
    for (int st = 64; st > 0; st >>= 1) {
        if (t < st) { s0[t] += s0[t + st]; s1[t] += s1[t + st]; s2[t] += s2[t + st]; }
        __syncthreads();
    }
    if (t == 0) {
        float x0 = s0[0] + b2[0];
        float x1 = s1[0] + b2[1];
        float x2 = s2[0] + b2[2];
        float m = fmaxf(x0, fmaxf(x1, x2));
        float l = logf(expf(x0 - m) + expf(x1 - m) + expf(x2 - m));
        out[row * 3 + 0] = x0 - m - l;
        out[row * 3 + 1] = x1 - m - l;
        out[row * 3 + 2] = x2 - m - l;
    }
}

// ---------------- host ----------------
#define SYM(p, s) cudaGetSymbolAddress((void**)&(p), s)

extern "C" void kernel_launch(void* const* d_in, const int* in_sizes, int n_in,
                              void* d_out, int out_size) {
    const float* features  = (const float*)d_in[0];
    const float* adj_ori   = (const float*)d_in[1];
    const float* mp_pap    = (const float*)d_in[2];
    const float* mp_psp    = (const float*)d_in[3];
    // d_in[4] enc_W, d_in[5] enc_b : unused (dead code in reference)
    const float* fgo_w     = (const float*)d_in[6];
    const float* fpo_w     = (const float*)d_in[7];
    const float* sgg_pap_w = (const float*)d_in[8];
    const float* sgg_psp_w = (const float*)d_in[9];
    const float* sg_agg_w  = (const float*)d_in[10];
    const float* f_agg_f_w = (const float*)d_in[11];
    const float* f_agg_w   = (const float*)d_in[12];
    const float* topo_W_a  = (const float*)d_in[13];
    const float* topo_b_a  = (const float*)d_in[14];
    const float* topo_W_s  = (const float*)d_in[15];
    const float* topo_b_s  = (const float*)d_in[16];
    const float* fgt_w_a   = (const float*)d_in[17];
    const float* fgt_w_s   = (const float*)d_in[18];
    const float* gcn_W1    = (const float*)d_in[19];
    const float* gcn_b1    = (const float*)d_in[20];
    const float* gcn_W2    = (const float*)d_in[21];
    const float* gcn_b2    = (const float*)d_in[22];

    float *Yt, *Ya, *Ys, *Ypap, *Ypsp, *Yfpa, *Yfps, *Ytha, *Yths;
    float *Mg, *Mpap, *Mpsp, *Mfa, *Mfs, *Msa, *Mss, *simA, *simS;
    float *fpA, *fpS, *HA, *HS, *thA, *thS;
    int *idxA, *idxS, *cntA, *cntS;
    float *valA, *valS, *cs, *alpha, *cspre, *rspre, *XW1, *X1, *Z2;

    SYM(Yt, g_Yt); SYM(Ya, g_Ya); SYM(Ys, g_Ys);
    SYM(Ypap, g_Ypap); SYM(Ypsp, g_Ypsp);
    SYM(Yfpa, g_Yfpa); SYM(Yfps, g_Yfps);
    SYM(Ytha, g_Ytha); SYM(Yths, g_Yths);
    SYM(Mg, g_Mg); SYM(Mpap, g_Mpap); SYM(Mpsp, g_Mpsp);
    SYM(Mfa, g_Mfa); SYM(Mfs, g_Mfs); SYM(Msa, g_Msa); SYM(Mss, g_Mss);
    SYM(simA, g_simA); SYM(simS, g_simS);
    SYM(fpA, g_fpA); SYM(fpS, g_fpS);
    SYM(HA, g_HA); SYM(HS, g_HS);
    SYM(thA, g_thA); SYM(thS, g_thS);
    SYM(idxA, g_idxA); SYM(idxS, g_idxS);
    SYM(valA, g_valA); SYM(valS, g_valS);
    SYM(cntA, g_cntA); SYM(cntS, g_cntS);
    SYM(cs, g_cs); SYM(alpha, g_alpha);
    SYM(cspre, g_cspre); SYM(rspre, g_rspre);
    SYM(XW1, g_XW1); SYM(X1, g_X1); SYM(Z2, g_Z2);

    float* pre = simA;   // simA is dead after HA GEMM; reuse as 'pre'

    // Output layout: [logits (4096x3) | new_adj (4096x4096)] when out_size covers both.
    float* out_logits = (float*)d_out;
    float* out_adj = (out_size >= NT * 3 + NT * NT) ? (float*)d_out + NT * 3 : Mg;

    cudaMemsetAsync(cs, 0, 7 * NT * sizeof(float));
    cudaMemsetAsync(rspre, 0, NT * sizeof(float));

    // sparse structure of adj_ori relation blocks (deterministic, ordered)
    compact_adj_kernel<<<NT / 8, 256>>>(adj_ori, NALL, NT, NA, idxA, valA, cntA);
    compact_adj_kernel<<<NT / 8, 256>>>(adj_ori, NALL, NT + NA, NS, idxS, valS, cntS);

    // packed per-head normalized features
    build_y_kernel<<<NT, 128>>>(features, fgo_w, FEAT, Yt);
    build_y_kernel<<<NA, 128>>>(features + (size_t)NT * FEAT, fgo_w, FEAT, Ya);
    build_y_kernel<<<NS, 128>>>(features + (size_t)(NT + NA) * FEAT, fgo_w, FEAT, Ys);
    build_y_kernel<<<NT, 128>>>(mp_pap, sgg_pap_w, MPD, Ypap);
    build_y_kernel<<<NT, 128>>>(mp_psp, sgg_psp_w, MPD, Ypsp);

    // feat_prop = ori_g @ fmat_r (sparse)
    sp_gather_kernel<<<NT, 128>>>(idxA, valA, cntA, features + (size_t)NT * FEAT, FEAT, nullptr, fpA);
    sp_gather_kernel<<<NT, 128>>>(idxS, valS, cntS, features + (size_t)(NT + NA) * FEAT, FEAT, nullptr, fpS);
    build_y_kernel<<<NT, 128>>>(fpA, fpo_w, FEAT, Yfpa);
    build_y_kernel<<<NT, 128>>>(fpS, fpo_w, FEAT, Yfps);

    // sim_r for both relations (triangular+mirror), then H = sim_r @ topo_W
    syrk_thresh_kernel<<<dim3(32, 32), 256>>>(Ya, NA, 256, 0.5f, FGH_TH, simA, nullptr);
    syrk_thresh_kernel<<<dim3(8, 8),   256>>>(Ys, NS, 256, 0.5f, FGH_TH, simS, nullptr);
    gemm_n64_kernel<<<64, 256>>>(simA, topo_W_a, nullptr, HA, NA, NA, 0);
    gemm_n64_kernel<<<16, 256>>>(simS, topo_W_s, nullptr, HS, NS, NS, 0);

    // topo_hid = ori_g @ H + b (sparse)
    sp_gather_kernel<<<NT, 64>>>(idxA, valA, cntA, HA, COM, topo_b_a, thA);
    sp_gather_kernel<<<NT, 64>>>(idxS, valS, cntS, HS, COM, topo_b_s, thS);
    build_y_kernel<<<NT, 128>>>(thA, fgt_w_a, COM, Ytha);
    build_y_kernel<<<NT, 128>>>(thS, fgt_w_s, COM, Yths);

    // the 7 channel matrices with fused colsums
    syrk_thresh_kernel<<<dim3(32, 32), 256>>>(Yt,   NT, 256, 0.5f, FGH_TH, Mg,   cs + 0 * NT);
    syrk_thresh_kernel<<<dim3(32, 32), 256>>>(Ypap, NT, 128, 0.5f, SEM_TH, Mpap, cs + 1 * NT);
    syrk_thresh_kernel<<<dim3(32, 32), 256>>>(Ypsp, NT, 128, 0.5f, SEM_TH, Mpsp, cs + 2 * NT);
    syrk_thresh_kernel<<<dim3(32, 32), 256>>>(Yfpa, NT, 256, 0.5f, FGP_TH, Mfa,  cs + 3 * NT);
    syrk_thresh_kernel<<<dim3(32, 32), 256>>>(Yfps, NT, 256, 0.5f, FGP_TH, Mfs,  cs + 4 * NT);
    syrk_thresh_kernel<<<dim3(32, 32), 256>>>(Ytha, NT, 128, 0.5f, FGH_TH, Msa,  cs + 5 * NT);
    syrk_thresh_kernel<<<dim3(32, 32), 256>>>(Yths, NT, 128, 0.5f, FGH_TH, Mss,  cs + 6 * NT);

    // channel-attention coefficients + analytic pre-colsum
    alpha_kernel<<<(NT + 255) / 256, 256>>>(cs, sg_agg_w, f_agg_f_w, f_agg_w, alpha, cspre);

    // weighted combine (overwrites simA as 'pre') + row sums
    combine_kernel<<<dim3(NT / 32, NT / 128), dim3(32, 8)>>>(
        Mg, Mpap, Mpsp, Mfa, Mfs, Msa, Mss, alpha, pre, rspre);

    // symmetrize + column-L1-normalize -> out_adj (Mg dead after combine)
    symnorm_kernel<<<dim3(NT / 32, NT / 32), dim3(32, 8)>>>(pre, cspre, rspre, out_adj);

    // GCN
    gemm_n64_kernel<<<64, 256>>>(features, gcn_W1, nullptr, XW1, NT, FEAT, 0);
    gemm_n64_kernel<<<64, 256>>>(out_adj, XW1, gcn_b1, X1, NT, NT, 1);
    xw2_kernel<<<(NT + 255) / 256, 256>>>(X1, gcn_W2, Z2);
    final_logits_kernel<<<NT, 128>>>(out_adj, Z2, gcn_b2, out_logits);
}

// round 11
// speedup vs baseline: 1.2631x; 1.2631x over previous
#include <cuda_runtime.h>
#include <math.h>

#define NT 4096
#define NA 4096
#define NS 1024
#define NALL 9216
#define FEAT 128
#define COM 64
#define MPD 64
#define MAXN 192
#define FGH_TH 0.1f
#define FGP_TH 0.2f
#define SEM_TH 0.1f

// ---------------- scratch (device globals; no allocations allowed) ----------------
__device__ float g_Yt  [NT * 256];
__device__ float g_Ya  [NA * 256];
__device__ float g_Ys  [NS * 256];
__device__ float g_Ypap[NT * 128];
__device__ float g_Ypsp[NT * 128];
__device__ float g_Yfpa[NT * 256];
__device__ float g_Yfps[NT * 256];
__device__ float g_Ytha[NT * 128];
__device__ float g_Yths[NT * 128];

__device__ float g_Mg  [16777216];
__device__ float g_Mpap[16777216];
__device__ float g_Mpsp[16777216];
__device__ float g_Mfa [16777216];   // also scratch for X1 split-K partials (dead after combine)
__device__ float g_Mfs [16777216];   // also scratch for HA split-K partials (written later)
__device__ float g_Msa [16777216];   // also scratch for HS split-K partials (written later)
__device__ float g_Mss [16777216];
__device__ float g_simA[16777216];   // reused later as 'pre' (dead after HA GEMM)
__device__ float g_simS[NS * NS];

__device__ float g_fpA[NT * FEAT];
__device__ float g_fpS[NT * FEAT];
__device__ float g_HA [NA * COM];
__device__ float g_HS [NS * COM];
__device__ float g_thA[NT * COM];
__device__ float g_thS[NT * COM];

__device__ int   g_idxA[NT * MAXN];
__device__ int   g_idxS[NT * MAXN];
__device__ float g_valA[NT * MAXN];
__device__ float g_valS[NT * MAXN];
__device__ int   g_cntA[NT];
__device__ int   g_cntS[NT];

__device__ float g_cs   [7 * NT];
__device__ float g_alpha[7 * NT];
__device__ float g_cspre[NT];
__device__ float g_rspre[NT];

__device__ float g_XW1[NT * 64];
__device__ float g_X1 [NT * 64];
__device__ float g_Z2 [NT * 3];

// ---------------- kernels ----------------

// zero cs (7*NT) and rspre (NT) in one launch (keeps all graph nodes as kernels
// so the ncu -s 5 -c 1 capture lands on a known launch index).
__global__ void zero_kernel(float* __restrict__ cs, float* __restrict__ rspre) {
    int i = blockIdx.x * blockDim.x + threadIdx.x;
    if (i < 7 * NT) cs[i] = 0.0f;
    else if (i < 8 * NT) rspre[i - 7 * NT] = 0.0f;
}

// Per-head weighted row-L2-normalize + pack: Y[row, h*D + d] = x_d*w_hd / max(||x∘w_h||,1e-12)
__global__ void build_y_kernel(const float* __restrict__ X, const float* __restrict__ W,
                               int D, float* __restrict__ Y) {
    int row = blockIdx.x;
    int t = threadIdx.x;             // 128 threads
    __shared__ float red[128];
    for (int h = 0; h < 2; h++) {
        float v = 0.0f;
        if (t < D) v = X[(size_t)row * D + t] * W[h * D + t];
        red[t] = v * v;
        __syncthreads();
        for (int s = 64; s > 0; s >>= 1) {
            if (t < s) red[t] += red[t + s];
            __syncthreads();
        }
        float nrm = fmaxf(sqrtf(red[0]), 1e-12f);
        __syncthreads();
        if (t < D) Y[(size_t)row * (2 * D) + h * D + t] = v / nrm;
    }
}

// Deterministic nonzero compaction (warp-per-row, ballot prefix -> ascending order).
__global__ void compact_adj_kernel(const float* __restrict__ adj, int lda, int col0, int ncols,
                                   int* __restrict__ idx, float* __restrict__ val,
                                   int* __restrict__ cnt) {
    int row = blockIdx.x * (blockDim.x / 32) + (threadIdx.x >> 5);
    int lane = threadIdx.x & 31;
    if (row >= NT) return;
    const float* base = adj + (size_t)row * lda + col0;
    int c = 0;
    for (int b = 0; b < ncols; b += 32) {
        int j = b + lane;
        float a = base[j];                   // ncols is a multiple of 32
        unsigned m = __ballot_sync(0xffffffffu, a != 0.0f);
        if (a != 0.0f) {
            int p = c + __popc(m & ((1u << lane) - 1u));
            if (p < MAXN) {
                idx[(size_t)row * MAXN + p] = j;
                val[(size_t)row * MAXN + p] = a;
            }
        }
        c += __popc(m);
    }
    if (lane == 0) cnt[row] = (c < MAXN) ? c : MAXN;
}

// dst[row,:] = sum_nbr val * src[nbr,:] (+ bias). blockDim.x == W.
__global__ void sp_gather_kernel(const int* __restrict__ idx, const float* __restrict__ val,
                                 const int* __restrict__ cnt, const float* __restrict__ src,
                                 int W, const float* __restrict__ bias, float* __restrict__ dst) {
    int row = blockIdx.x;
    int t = threadIdx.x;
    float acc = bias ? bias[t] : 0.0f;
    int n = cnt[row];
    const int* ip = idx + (size_t)row * MAXN;
    const float* vp = val + (size_t)row * MAXN;
    for (int p = 0; p < n; p++) {
        acc += vp[p] * src[(size_t)ip[p] * W + t];
    }
    dst[(size_t)row * W + t] = acc;
}

// Triangular SYRK: C = thresh(scale * Y Y^T, th), exact-symmetric mirror of
// off-diagonal tiles, fused full-matrix row sums (== col sums) into colsum.
// 128x128 tile, BK=16, 256 threads, 8x8 per thread (split-64 conflict-free mapping).
__global__ __launch_bounds__(256) void syrk_thresh_kernel(
    const float* __restrict__ Y, int N, int K, float scale, float th,
    float* __restrict__ C, float* __restrict__ colsum) {
    int bi = blockIdx.y, bj = blockIdx.x;
    if (bj < bi) return;
    __shared__ float As[16][128];
    __shared__ float Bs[16][128];
    __shared__ float s_col[128];
    int tid = threadIdx.x;
    int tx = tid & 15, ty = tid >> 4;
    const float* Arow = Y + (size_t)bi * 128 * K;
    const float* Brow = Y + (size_t)bj * 128 * K;
    float acc[8][8];
#pragma unroll
    for (int i = 0; i < 8; i++)
#pragma unroll
        for (int j = 0; j < 8; j++) acc[i][j] = 0.0f;

    for (int k0 = 0; k0 < K; k0 += 16) {
#pragma unroll
        for (int l = 0; l < 2; l++) {
            int f = tid * 2 + l;     // 0..511
            int r = f >> 2;
            int q = f & 3;
            float4 a = *(const float4*)(Arow + (size_t)r * K + k0 + q * 4);
            As[q * 4 + 0][r] = a.x; As[q * 4 + 1][r] = a.y;
            As[q * 4 + 2][r] = a.z; As[q * 4 + 3][r] = a.w;
            float4 b = *(const float4*)(Brow + (size_t)r * K + k0 + q * 4);
            Bs[q * 4 + 0][r] = b.x; Bs[q * 4 + 1][r] = b.y;
            Bs[q * 4 + 2][r] = b.z; Bs[q * 4 + 3][r] = b.w;
        }
        __syncthreads();
#pragma unroll
        for (int k = 0; k < 16; k++) {
            float4 a0 = *(const float4*)&As[k][ty * 4];
            float4 a1 = *(const float4*)&As[k][64 + ty * 4];
            float4 b0 = *(const float4*)&Bs[k][tx * 4];
            float4 b1 = *(const float4*)&Bs[k][64 + tx * 4];
            float av[8] = {a0.x, a0.y, a0.z, a0.w, a1.x, a1.y, a1.z, a1.w};
            float bv[8] = {b0.x, b0.y, b0.z, b0.w, b1.x, b1.y, b1.z, b1.w};
#pragma unroll
            for (int i = 0; i < 8; i++)
#pragma unroll
                for (int j = 0; j < 8; j++) acc[i][j] += av[i] * bv[j];
        }
        __syncthreads();
    }

    // threshold in place
#pragma unroll
    for (int i = 0; i < 8; i++)
#pragma unroll
        for (int j = 0; j < 8; j++) {
            float c = acc[i][j] * scale;
            acc[i][j] = (c < th) ? 0.0f : c;
        }

    // direct tile store (rows bi-block, cols bj-block) + row sums
#pragma unroll
    for (int ri = 0; ri < 2; ri++) {
#pragma unroll
        for (int ii = 0; ii < 4; ii++) {
            int i = ri * 4 + ii;
            int row = bi * 128 + ri * 64 + ty * 4 + ii;
            float4 w0 = make_float4(acc[i][0], acc[i][1], acc[i][2], acc[i][3]);
            float4 w1 = make_float4(acc[i][4], acc[i][5], acc[i][6], acc[i][7]);
            *(float4*)(C + (size_t)row * N + bj * 128 + tx * 4) = w0;
            *(float4*)(C + (size_t)row * N + bj * 128 + 64 + tx * 4) = w1;
            if (colsum) {
                float rs = w0.x + w0.y + w0.z + w0.w + w1.x + w1.y + w1.z + w1.w;
#pragma unroll
                for (int off = 8; off >= 1; off >>= 1)
                    rs += __shfl_down_sync(0xffffffffu, rs, off, 16);
                if (tx == 0) atomicAdd(&colsum[row], rs);
            }
        }
    }

    if (bi != bj) {
        // mirror store: transposed tile to (bj-block rows, bi-block cols).
#pragma unroll
        for (int ci = 0; ci < 2; ci++) {
#pragma unroll
            for (int jj = 0; jj < 4; jj++) {
                int j = ci * 4 + jj;
                int r2 = bj * 128 + ci * 64 + tx * 4 + jj;
                float4 w0 = make_float4(acc[0][j], acc[1][j], acc[2][j], acc[3][j]);
                float4 w1 = make_float4(acc[4][j], acc[5][j], acc[6][j], acc[7][j]);
                *(float4*)(C + (size_t)r2 * N + bi * 128 + ty * 4) = w0;
                *(float4*)(C + (size_t)r2 * N + bi * 128 + 64 + ty * 4) = w1;
            }
        }
        if (colsum) {
            // mirror rows' sums == direct tile column sums
            if (tid < 128) s_col[tid] = 0.0f;
            __syncthreads();
#pragma unroll
            for (int ci = 0; ci < 2; ci++)
#pragma unroll
                for (int jj = 0; jj < 4; jj++) {
                    int j = ci * 4 + jj;
                    float cp = 0.0f;
#pragma unroll
                    for (int i = 0; i < 8; i++) cp += acc[i][j];
                    atomicAdd(&s_col[ci * 64 + tx * 4 + jj], cp);
                }
            __syncthreads();
            if (tid < 128) atomicAdd(&colsum[bj * 128 + tid], s_col[tid]);
        }
    }
}

// C[M,64] = A[M,K] @ B[K,64] (+bias, optional relu). 64x64 tile, BK=32.
__global__ __launch_bounds__(256) void gemm_n64_kernel(
    const float* __restrict__ A, const float* __restrict__ B,
    const float* __restrict__ bias, float* __restrict__ C,
    int M, int K, int relu) {
    __shared__ float As[32][65];
    __shared__ float Bs[32][64];
    int bm = blockIdx.x;
    int tid = threadIdx.x;
    int tx = tid & 15, ty = tid >> 4;
    float acc[4][4];
#pragma unroll
    for (int i = 0; i < 4; i++)
#pragma unroll
        for (int j = 0; j < 4; j++) acc[i][j] = 0.0f;

    for (int k0 = 0; k0 < K; k0 += 32) {
#pragma unroll
        for (int l = 0; l < 2; l++) {
            int f = tid * 2 + l;
            int r = f >> 3;
            int q = f & 7;
            float4 a = *(const float4*)(A + (size_t)(bm * 64 + r) * K + k0 + q * 4);
            As[q * 4 + 0][r] = a.x; As[q * 4 + 1][r] = a.y;
            As[q * 4 + 2][r] = a.z; As[q * 4 + 3][r] = a.w;
            int kr = f >> 4;
            int nq = f & 15;
            float4 b = *(const float4*)(B + (size_t)(k0 + kr) * 64 + nq * 4);
            *(float4*)&Bs[kr][nq * 4] = b;
        }
        __syncthreads();
#pragma unroll
        for (int k = 0; k < 32; k++) {
            float a[4], b[4];
#pragma unroll
            for (int i = 0; i < 4; i++) a[i] = As[k][ty * 4 + i];
#pragma unroll
            for (int j = 0; j < 4; j++) b[j] = Bs[k][tx * 4 + j];
#pragma unroll
            for (int i = 0; i < 4; i++)
#pragma unroll
                for (int j = 0; j < 4; j++) acc[i][j] += a[i] * b[j];
        }
        __syncthreads();
    }
#pragma unroll
    for (int i = 0; i < 4; i++) {
        int row = bm * 64 + ty * 4 + i;
        float v[4];
#pragma unroll
        for (int j = 0; j < 4; j++) {
            float c = acc[i][j];
            if (bias) c += bias[tx * 4 + j];
            if (relu) c = fmaxf(c, 0.0f);
            v[j] = c;
        }
        *(float4*)(C + (size_t)row * 64 + tx * 4) = make_float4(v[0], v[1], v[2], v[3]);
    }
}

// Split-K partial GEMM: part[s][M,64] = A[:, s*KS:(s+1)*KS] @ B[s*KS:...,:64].
// Same tiling as gemm_n64; grid (M/64, S).
__global__ __launch_bounds__(256) void gemm_n64_splitk_kernel(
    const float* __restrict__ A, const float* __restrict__ B,
    float* __restrict__ part, int M, int K, int KS) {
    __shared__ float As[32][65];
    __shared__ float Bs[32][64];
    int bm = blockIdx.x;
    int s = blockIdx.y;
    int kbase = s * KS;
    int tid = threadIdx.x;
    int tx = tid & 15, ty = tid >> 4;
    float acc[4][4];
#pragma unroll
    for (int i = 0; i < 4; i++)
#pragma unroll
        for (int j = 0; j < 4; j++) acc[i][j] = 0.0f;

    for (int kk = 0; kk < KS; kk += 32) {
        int k0 = kbase + kk;
#pragma unroll
        for (int l = 0; l < 2; l++) {
            int f = tid * 2 + l;
            int r = f >> 3;
            int q = f & 7;
            float4 a = *(const float4*)(A + (size_t)(bm * 64 + r) * K + k0 + q * 4);
            As[q * 4 + 0][r] = a.x; As[q * 4 + 1][r] = a.y;
            As[q * 4 + 2][r] = a.z; As[q * 4 + 3][r] = a.w;
            int kr = f >> 4;
            int nq = f & 15;
            float4 b = *(const float4*)(B + (size_t)(k0 + kr) * 64 + nq * 4);
            *(float4*)&Bs[kr][nq * 4] = b;
        }
        __syncthreads();
#pragma unroll
        for (int k = 0; k < 32; k++) {
            float a[4], b[4];
#pragma unroll
            for (int i = 0; i < 4; i++) a[i] = As[k][ty * 4 + i];
#pragma unroll
            for (int j = 0; j < 4; j++) b[j] = Bs[k][tx * 4 + j];
#pragma unroll
            for (int i = 0; i < 4; i++)
#pragma unroll
                for (int j = 0; j < 4; j++) acc[i][j] += a[i] * b[j];
        }
        __syncthreads();
    }
    float* base = part + (size_t)s * M * 64;
#pragma unroll
    for (int i = 0; i < 4; i++) {
        int row = bm * 64 + ty * 4 + i;
        *(float4*)(base + (size_t)row * 64 + tx * 4) =
            make_float4(acc[i][0], acc[i][1], acc[i][2], acc[i][3]);
    }
}

// C[i] = sum_s part[s][i] (+bias, optional relu); deterministic sequential sum.
__global__ void splitk_reduce_kernel(const float* __restrict__ part, int M,
                                     const float* __restrict__ bias, int relu,
                                     float* __restrict__ C) {
    int i = blockIdx.x * blockDim.x + threadIdx.x;
    int total = M * 64;
    if (i >= total) return;
    size_t stride = (size_t)M * 64;
    float v = part[i] + part[stride + i] + part[2 * stride + i] + part[3 * stride + i];
    if (bias) v += bias[i & 63];
    if (relu) v = fmaxf(v, 0.0f);
    C[i] = v;
}

// Per-column channel-attention coefficients from the 7 colsums + softmaxed weights.
__global__ void alpha_kernel(const float* __restrict__ cs,
                             const float* __restrict__ sg_w, const float* __restrict__ ff_w,
                             const float* __restrict__ f_w,
                             float* __restrict__ alpha, float* __restrict__ cspre) {
    int j = blockIdx.x * blockDim.x + threadIdx.x;
    if (j >= NT) return;
    const float eps = 1e-12f;
    float m1 = fmaxf(sg_w[0], sg_w[1]);
    float e0 = expf(sg_w[0] - m1), e1 = expf(sg_w[1] - m1);
    float wi0 = e0 / (e0 + e1), wi1 = e1 / (e0 + e1);
    float m2 = fmaxf(ff_w[0], ff_w[1]);
    float f0 = expf(ff_w[0] - m2), f1 = expf(ff_w[1] - m2);
    float wf0 = f0 / (f0 + f1), wf1 = f1 / (f0 + f1);
    float m3 = fmaxf(fmaxf(f_w[0], f_w[1]), fmaxf(f_w[2], f_w[3]));
    float o0 = expf(f_w[0] - m3), o1 = expf(f_w[1] - m3);
    float o2 = expf(f_w[2] - m3), o3 = expf(f_w[3] - m3);
    float os = o0 + o1 + o2 + o3;
    float wo0 = o0 / os, wo1 = o1 / os, wo2 = o2 / os, wo3 = o3 / os;

    float cg   = cs[0 * NT + j];
    float cpap = cs[1 * NT + j];
    float cpsp = cs[2 * NT + j];
    float cfa  = cs[3 * NT + j];
    float cfs  = cs[4 * NT + j];
    float csa  = cs[5 * NT + j];
    float css  = cs[6 * NT + j];

    float bpap = cpap / fmaxf(cpap, eps);
    float bpsp = cpsp / fmaxf(cpsp, eps);
    float bfa  = cfa  / fmaxf(cfa,  eps);
    float bfs  = cfs  / fmaxf(cfs,  eps);
    float bsa  = csa  / fmaxf(csa,  eps);
    float bss  = css  / fmaxf(css,  eps);

    float csem = wi0 * bpap + wi1 * bpsp;
    float cfp  = wf0 * bfa  + wf1 * bfs;
    float ctt  = wf0 * bsa  + wf1 * bss;

    float ag   = wo0 / fmaxf(cg, eps);
    float apap = wo1 * wi0 / fmaxf(cpap, eps) / fmaxf(csem, eps);
    float apsp = wo1 * wi1 / fmaxf(cpsp, eps) / fmaxf(csem, eps);
    float afa  = wo2 * wf0 / fmaxf(cfa,  eps) / fmaxf(cfp,  eps);
    float afs  = wo2 * wf1 / fmaxf(cfs,  eps) / fmaxf(cfp,  eps);
    float asa  = wo3 * wf0 / fmaxf(csa,  eps) / fmaxf(ctt,  eps);
    float ass  = wo3 * wf1 / fmaxf(css,  eps) / fmaxf(ctt,  eps);

    alpha[0 * NT + j] = ag;
    alpha[1 * NT + j] = apap;
    alpha[2 * NT + j] = apsp;
    alpha[3 * NT + j] = afa;
    alpha[4 * NT + j] = afs;
    alpha[5 * NT + j] = asa;
    alpha[6 * NT + j] = ass;
    cspre[j] = ag * cg + apap * cpap + apsp * cpsp + afa * cfa + afs * cfs
             + asa * csa + ass * css;
}

// pre[i,j] = sum_m alpha_m[j] * M_m[i,j]; accumulate row sums of pre.
__global__ void combine_kernel(const float* __restrict__ M0, const float* __restrict__ M1,
                               const float* __restrict__ M2, const float* __restrict__ M3,
                               const float* __restrict__ M4, const float* __restrict__ M5,
                               const float* __restrict__ M6,
                               const float* __restrict__ alpha,
                               float* __restrict__ pre, float* __restrict__ rowsum) {
    int j = blockIdx.x * 32 + threadIdx.x;
    float a0 = alpha[0 * NT + j];
    float a1 = alpha[1 * NT + j];
    float a2 = alpha[2 * NT + j];
    float a3 = alpha[3 * NT + j];
    float a4 = alpha[4 * NT + j];
    float a5 = alpha[5 * NT + j];
    float a6 = alpha[6 * NT + j];
#pragma unroll
    for (int r = 0; r < 16; r++) {
        int i = blockIdx.y * 128 + threadIdx.y + r * 8;
        size_t off = (size_t)i * NT + j;
        float v = a0 * M0[off] + a1 * M1[off] + a2 * M2[off] + a3 * M3[off]
                + a4 * M4[off] + a5 * M5[off] + a6 * M6[off];
        pre[off] = v;
        float s = v;
#pragma unroll
        for (int o = 16; o >= 1; o >>= 1) s += __shfl_down_sync(0xffffffffu, s, o);
        if (threadIdx.x == 0) atomicAdd(&rowsum[i], s);
    }
}

// out[i,j] = (pre[i,j] + pre[j,i]) / max(cspre[j] + rspre[j], 1e-12)
__global__ void symnorm_kernel(const float* __restrict__ pre, const float* __restrict__ cspre,
                               const float* __restrict__ rspre, float* __restrict__ out) {
    __shared__ float tile[32][33];
    int bi = blockIdx.y, bj = blockIdx.x;
    int x = threadIdx.x, y = threadIdx.y;
#pragma unroll
    for (int r = 0; r < 4; r++) {
        int yy = y + r * 8;
        tile[yy][x] = pre[(size_t)(bj * 32 + yy) * NT + bi * 32 + x];
    }
    __syncthreads();
#pragma unroll
    for (int r = 0; r < 4; r++) {
        int i = bi * 32 + y + r * 8;
        int j = bj * 32 + x;
        float d = fmaxf(cspre[j] + rspre[j], 1e-12f);
        float v = (pre[(size_t)i * NT + j] + tile[x][y + r * 8]) / d;
        out[(size_t)i * NT + j] = v;
    }
}

// Z2 = X1[4096,64] @ W2[64,3]
__global__ void xw2_kernel(const float* __restrict__ X1, const float* __restrict__ W2,
                           float* __restrict__ Z2) {
    int row = blockIdx.x * blockDim.x + threadIdx.x;
    if (row >= NT) return;
    float a0 = 0, a1 = 0, a2 = 0;
    const float* x = X1 + (size_t)row * 64;
#pragma unroll 8
    for (int k = 0; k < 64; k++) {
        float v = x[k];
        a0 += v * W2[k * 3 + 0];
        a1 += v * W2[k * 3 + 1];
        a2 += v * W2[k * 3 + 2];
    }
    Z2[row * 3 + 0] = a0;
    Z2[row * 3 + 1] = a1;
    Z2[row * 3 + 2] = a2;
}

// logits[row,:] = log_softmax(adj[row,:] @ Z2 + b2)
__global__ void final_logits_kernel(const float* __restrict__ adj, const float* __restrict__ Z2,
                                    const float* __restrict__ b2, float* __restrict__ out) {
    int row = blockIdx.x;
    int t = threadIdx.x;   // 128
    float a0 = 0, a1 = 0, a2 = 0;
    const float* ar = adj + (size_t)row * NT;
    for (int k = t; k < NT; k += 128) {
        float w = ar[k];
        a0 += w * Z2[k * 3 + 0];
        a1 += w * Z2[k * 3 + 1];
        a2 += w * Z2[k * 3 + 2];
    }
    __shared__ float s0[128], s1[128], s2[128];
    s0[t] = a0; s1[t] = a1; s2[t] = a2;
    __syncthreads();
    for (int st = 64; st > 0; st >>= 1) {
        if (t < st) { s0[t] += s0[t + st]; s1[t] += s1[t + st]; s2[t] += s2[t + st]; }
        __syncthreads();
    }
    if (t == 0) {
        float x0 = s0[0] + b2[0];
        float x1 = s1[0] + b2[1];
        float x2 = s2[0] + b2[2];
        float m = fmaxf(x0, fmaxf(x1, x2));
        float l = logf(expf(x0 - m) + expf(x1 - m) + expf(x2 - m));
        out[row * 3 + 0] = x0 - m - l;
        out[row * 3 + 1] = x1 - m - l;
        out[row * 3 + 2] = x2 - m - l;
    }
}

// ---------------- host ----------------
#define SYM(p, s) cudaGetSymbolAddress((void**)&(p), s)

extern "C" void kernel_launch(void* const* d_in, const int* in_sizes, int n_in,
                              void* d_out, int out_size) {
    const float* features  = (const float*)d_in[0];
    const float* adj_ori   = (const float*)d_in[1];
    const float* mp_pap    = (const float*)d_in[2];
    const float* mp_psp    = (const float*)d_in[3];
    // d_in[4] enc_W, d_in[5] enc_b : unused (dead code in reference)
    const float* fgo_w     = (const float*)d_in[6];
    const float* fpo_w     = (const float*)d_in[7];
    const float* sgg_pap_w = (const float*)d_in[8];
    const float* sgg_psp_w = (const float*)d_in[9];
    const float* sg_agg_w  = (const float*)d_in[10];
    const float* f_agg_f_w = (const float*)d_in[11];
    const float* f_agg_w   = (const float*)d_in[12];
    const float* topo_W_a  = (const float*)d_in[13];
    const float* topo_b_a  = (const float*)d_in[14];
    const float* topo_W_s  = (const float*)d_in[15];
    const float* topo_b_s  = (const float*)d_in[16];
    const float* fgt_w_a   = (const float*)d_in[17];
    const float* fgt_w_s   = (const float*)d_in[18];
    const float* gcn_W1    = (const float*)d_in[19];
    const float* gcn_b1    = (const float*)d_in[20];
    const float* gcn_W2    = (const float*)d_in[21];
    const float* gcn_b2    = (const float*)d_in[22];

    float *Yt, *Ya, *Ys, *Ypap, *Ypsp, *Yfpa, *Yfps, *Ytha, *Yths;
    float *Mg, *Mpap, *Mpsp, *Mfa, *Mfs, *Msa, *Mss, *simA, *simS;
    float *fpA, *fpS, *HA, *HS, *thA, *thS;
    int *idxA, *idxS, *cntA, *cntS;
    float *valA, *valS, *cs, *alpha, *cspre, *rspre, *XW1, *X1, *Z2;

    SYM(Yt, g_Yt); SYM(Ya, g_Ya); SYM(Ys, g_Ys);
    SYM(Ypap, g_Ypap); SYM(Ypsp, g_Ypsp);
    SYM(Yfpa, g_Yfpa); SYM(Yfps, g_Yfps);
    SYM(Ytha, g_Ytha); SYM(Yths, g_Yths);
    SYM(Mg, g_Mg); SYM(Mpap, g_Mpap); SYM(Mpsp, g_Mpsp);
    SYM(Mfa, g_Mfa); SYM(Mfs, g_Mfs); SYM(Msa, g_Msa); SYM(Mss, g_Mss);
    SYM(simA, g_simA); SYM(simS, g_simS);
    SYM(fpA, g_fpA); SYM(fpS, g_fpS);
    SYM(HA, g_HA); SYM(HS, g_HS);
    SYM(thA, g_thA); SYM(thS, g_thS);
    SYM(idxA, g_idxA); SYM(idxS, g_idxS);
    SYM(valA, g_valA); SYM(valS, g_valS);
    SYM(cntA, g_cntA); SYM(cntS, g_cntS);
    SYM(cs, g_cs); SYM(alpha, g_alpha);
    SYM(cspre, g_cspre); SYM(rspre, g_rspre);
    SYM(XW1, g_XW1); SYM(X1, g_X1); SYM(Z2, g_Z2);

    float* pre = simA;   // simA is dead after HA GEMM; reuse as 'pre'

    float* out_logits = (float*)d_out;
    float* out_adj = (out_size >= NT * 3 + NT * NT) ? (float*)d_out + NT * 3 : Mg;

    // ---- launch order chosen so ncu (-s 5 -c 1) profiles launch idx 5: the K=256 SYRK ----
    zero_kernel<<<(8 * NT + 255) / 256, 256>>>(cs, rspre);                                   // 0
    compact_adj_kernel<<<NT / 8, 256>>>(adj_ori, NALL, NT, NA, idxA, valA, cntA);            // 1
    compact_adj_kernel<<<NT / 8, 256>>>(adj_ori, NALL, NT + NA, NS, idxS, valS, cntS);       // 2
    build_y_kernel<<<NT, 128>>>(features, fgo_w, FEAT, Yt);                                  // 3
    build_y_kernel<<<NA, 128>>>(features + (size_t)NT * FEAT, fgo_w, FEAT, Ya);              // 4
    syrk_thresh_kernel<<<dim3(32, 32), 256>>>(Yt, NT, 256, 0.5f, FGH_TH, Mg, cs + 0 * NT);   // 5 <- profiled

    build_y_kernel<<<NS, 128>>>(features + (size_t)(NT + NA) * FEAT, fgo_w, FEAT, Ys);
    build_y_kernel<<<NT, 128>>>(mp_pap, sgg_pap_w, MPD, Ypap);
    build_y_kernel<<<NT, 128>>>(mp_psp, sgg_psp_w, MPD, Ypsp);

    sp_gather_kernel<<<NT, 128>>>(idxA, valA, cntA, features + (size_t)NT * FEAT, FEAT, nullptr, fpA);
    sp_gather_kernel<<<NT, 128>>>(idxS, valS, cntS, features + (size_t)(NT + NA) * FEAT, FEAT, nullptr, fpS);
    build_y_kernel<<<NT, 128>>>(fpA, fpo_w, FEAT, Yfpa);
    build_y_kernel<<<NT, 128>>>(fpS, fpo_w, FEAT, Yfps);

    // sim_r for both relations, then H = sim_r @ topo_W (split-K x4, deterministic reduce)
    syrk_thresh_kernel<<<dim3(32, 32), 256>>>(Ya, NA, 256, 0.5f, FGH_TH, simA, nullptr);
    syrk_thresh_kernel<<<dim3(8, 8),   256>>>(Ys, NS, 256, 0.5f, FGH_TH, simS, nullptr);
    gemm_n64_splitk_kernel<<<dim3(64, 4), 256>>>(simA, topo_W_a, Mfs, NA, NA, NA / 4);  // Mfs scratch
    splitk_reduce_kernel<<<(NA * 64 + 255) / 256, 256>>>(Mfs, NA, nullptr, 0, HA);
    gemm_n64_splitk_kernel<<<dim3(16, 4), 256>>>(simS, topo_W_s, Msa, NS, NS, NS / 4);  // Msa scratch
    splitk_reduce_kernel<<<(NS * 64 + 255) / 256, 256>>>(Msa, NS, nullptr, 0, HS);

    // topo_hid = ori_g @ H + b (sparse)
    sp_gather_kernel<<<NT, 64>>>(idxA, valA, cntA, HA, COM, topo_b_a, thA);
    sp_gather_kernel<<<NT, 64>>>(idxS, valS, cntS, HS, COM, topo_b_s, thS);
    build_y_kernel<<<NT, 128>>>(thA, fgt_w_a, COM, Ytha);
    build_y_kernel<<<NT, 128>>>(thS, fgt_w_s, COM, Yths);

    // remaining channel matrices with fused colsums (Mg already done at launch 5)
    syrk_thresh_kernel<<<dim3(32, 32), 256>>>(Ypap, NT, 128, 0.5f, SEM_TH, Mpap, cs + 1 * NT);
    syrk_thresh_kernel<<<dim3(32, 32), 256>>>(Ypsp, NT, 128, 0.5f, SEM_TH, Mpsp, cs + 2 * NT);
    syrk_thresh_kernel<<<dim3(32, 32), 256>>>(Yfpa, NT, 256, 0.5f, FGP_TH, Mfa,  cs + 3 * NT);
    syrk_thresh_kernel<<<dim3(32, 32), 256>>>(Yfps, NT, 256, 0.5f, FGP_TH, Mfs,  cs + 4 * NT);
    syrk_thresh_kernel<<<dim3(32, 32), 256>>>(Ytha, NT, 128, 0.5f, FGH_TH, Msa,  cs + 5 * NT);
    syrk_thresh_kernel<<<dim3(32, 32), 256>>>(Yths, NT, 128, 0.5f, FGH_TH, Mss,  cs + 6 * NT);

    // channel-attention coefficients + analytic pre-colsum
    alpha_kernel<<<(NT + 255) / 256, 256>>>(cs, sg_agg_w, f_agg_f_w, f_agg_w, alpha, cspre);

    // weighted combine (overwrites simA as 'pre') + row sums
    combine_kernel<<<dim3(NT / 32, NT / 128), dim3(32, 8)>>>(
        Mg, Mpap, Mpsp, Mfa, Mfs, Msa, Mss, alpha, pre, rspre);

    // symmetrize + column-L1-normalize -> out_adj (Mg dead after combine)
    symnorm_kernel<<<dim3(NT / 32, NT / 32), dim3(32, 8)>>>(pre, cspre, rspre, out_adj);

    // GCN: XW1 small; X1 = adj @ XW1 via split-K x4 (Mfa dead after combine)
    gemm_n64_kernel<<<64, 256>>>(features, gcn_W1, nullptr, XW1, NT, FEAT, 0);
    gemm_n64_splitk_kernel<<<dim3(64, 4), 256>>>(out_adj, XW1, Mfa, NT, NT, NT / 4);
    splitk_reduce_kernel<<<(NT * 64 + 255) / 256, 256>>>(Mfa, NT, gcn_b1, 1, X1);
    xw2_kernel<<<(NT + 255) / 256, 256>>>(X1, gcn_W2, Z2);
    final_logits_kernel<<<NT, 128>>>(out_adj, Z2, gcn_b2, out_logits);
}